// round 6
// baseline (speedup 1.0000x reference)
#include <cuda_runtime.h>
#include <cstdint>
#include <cstddef>

// ModulatedConv2d: B=8, IC=256, OC=256, H=W=64, K=3, pad=1, style_dim=512, demod.
//
// out[b,o] = d[b,o] * conv( s'[b,i]*x[b,i], W[o,i] )
//   s'[b,i] = (style[b]·mod_w[i]*lin_scale + mod_b[i]) * conv_scale
//   d[b,o]  = rsqrt( sum_i s'[b,i]^2 * sum_t W[o,i,t]^2 + 1e-8 )
// One batch-independent implicit GEMM: M=8*4096 pixels, N=256 oc, K=2304.
// K ordered as [tap][ic] so the per-8k-tile gather is pure pointer stepping.

#define B_      8
#define IC_     256
#define OC_     256
#define NPIX    4096          // 64*64
#define KDIM    2304          // 9*256
#define KTILES  288           // 2304/8

static __device__ float g_s[B_ * IC_];            // s' (includes conv_scale)
static __device__ float g_d[B_ * OC_];            // demod factors
static __device__ float g_wt[KDIM * OC_];         // weight [tap*256+ic][oc]
static __device__ float g_xs[B_ * IC_ * NPIX];    // pre-scaled x (32 MB scratch)

#define LIN_SCALE  0.044194173824159216f   // 1/sqrt(512)
#define CONV_SCALE 0.020833333333333332f   // 1/48 = 1/sqrt(256*9)

// ---------------- prep 1: styles (one warp per (b,c)) ----------------
__global__ void style_kernel(const float* __restrict__ style,
                             const float* __restrict__ mod_w,
                             const float* __restrict__ mod_b) {
    int tid  = threadIdx.x;
    int lane = tid & 31;
    int gw   = blockIdx.x * 8 + (tid >> 5);   // 0..2047
    int b    = gw >> 8;
    int c    = gw & 255;
    const float* sp = style + b * 512;
    const float* mp = mod_w + c * 512;
    float acc = 0.f;
#pragma unroll
    for (int j = 0; j < 16; j++)
        acc += sp[lane + j * 32] * mp[lane + j * 32];
#pragma unroll
    for (int off = 16; off; off >>= 1)
        acc += __shfl_down_sync(0xffffffffu, acc, off);
    if (lane == 0)
        g_s[b * 256 + c] = (acc * LIN_SCALE + mod_b[c]) * CONV_SCALE;
}

// ---------------- prep 2: pre-scale x into g_xs ----------------
// 8M floats = 2M float4; (float4 idx) >> 10 == b*256+ic
__global__ void scale_x_kernel(const float* __restrict__ x) {
    int i = blockIdx.x * 256 + threadIdx.x;
    float s = g_s[i >> 10];
    float4 v = ((const float4*)x)[i];
    v.x *= s; v.y *= s; v.z *= s; v.w *= s;
    ((float4*)g_xs)[i] = v;
}

// ---------------- prep 3: transpose weight to [tap*256+ic][oc] ----------------
__global__ void wtrans_kernel(const float* __restrict__ W) {
    int k   = blockIdx.x;           // 0..2303 = tap*256 + ic
    int oc  = threadIdx.x;
    int tap = k >> 8;
    int ic  = k & 255;
    g_wt[k * 256 + oc] = W[oc * KDIM + ic * 9 + tap];
}

// ---------------- prep 4: demod factors ----------------
__global__ void demod_kernel(const float* __restrict__ W) {
    int o = blockIdx.x;
    int i = threadIdx.x;
    const float* wp = W + o * KDIM + i * 9;
    float wsq = 0.f;
#pragma unroll
    for (int t = 0; t < 9; t++) wsq += wp[t] * wp[t];

    __shared__ float red[256];
#pragma unroll 1
    for (int b = 0; b < B_; b++) {
        float sv = g_s[b * 256 + i];
        red[i] = sv * sv * wsq;
        __syncthreads();
#pragma unroll
        for (int s = 128; s > 0; s >>= 1) {
            if (i < s) red[i] += red[i + s];
            __syncthreads();
        }
        if (i == 0) g_d[b * 256 + o] = rsqrtf(red[0] + 1e-8f);
        __syncthreads();
    }
}

// ---------------- main implicit-GEMM conv ----------------
// grid (32, 2, 8), 256 threads, BM=128 (pixels), BN=128 (oc), BK=8,
// thread tile 8x8 via fma.rn.f32x2, double-buffered smem, 1 sync/tile.
__global__ __launch_bounds__(256, 2)
void conv_kernel(float* __restrict__ out) {
    const int b   = blockIdx.z;
    const int m0  = blockIdx.x * 128;
    const int n0  = blockIdx.y * 128;
    const int tid = threadIdx.x;
    const int tx  = tid & 15;
    const int ty  = tid >> 4;

    __shared__ __align__(16) float As[2][8][128];
    __shared__ __align__(16) float Bs[2][8][128];

    const float* xb = g_xs + ((size_t)b << 20);
    const int mm  = tid & 127;
    const int kk0 = tid >> 7;           // 0/1: this thread loads kk = kk0,+2,+4,+6
    const int m = m0 + mm;
    const int h = m >> 6;
    const int w = m & 63;

    unsigned long long acc[8][4];
#pragma unroll
    for (int i = 0; i < 8; i++)
#pragma unroll
        for (int j = 0; j < 4; j++) acc[i][j] = 0ull;

    float a_r[4], b_r[4];

    auto loadTiles = [&](int k0) {
        int tap = k0 >> 8;                       // constant over 32 tiles
        int t3  = (tap * 11) >> 5;               // tap/3 for 0..8
        int dh  = t3 - 1;
        int dw  = tap - t3 * 3 - 1;
        int hh  = h + dh, ww = w + dw;
        bool ok = ((unsigned)hh < 64u) & ((unsigned)ww < 64u);
        int ic0 = (k0 & 255) + kk0;
        const float* xp = xb + ic0 * 4096 + hh * 64 + ww;
        const float* wp = g_wt + (size_t)(k0 + kk0) * 256 + n0 + mm;
#pragma unroll
        for (int i = 0; i < 4; i++) {
            a_r[i] = ok ? __ldg(xp + i * 8192) : 0.f;     // +2 ic per i
            b_r[i] = __ldg(wp + i * 512);                 // +2 k  per i
        }
    };
    auto storeTiles = [&](int buf) {
#pragma unroll
        for (int i = 0; i < 4; i++) {
            int kk = kk0 + 2 * i;
            As[buf][kk][mm] = a_r[i];
            Bs[buf][kk][mm] = b_r[i];
        }
    };

    loadTiles(0);
    storeTiles(0);
    __syncthreads();

    int buf = 0;
#pragma unroll 1
    for (int kt = 0; kt < KTILES; kt++) {
        if (kt < KTILES - 1) loadTiles((kt + 1) * 8);

#pragma unroll
        for (int kk = 0; kk < 8; kk++) {
            float4 a0 = *(const float4*)&As[buf][kk][ty * 8];
            float4 a1 = *(const float4*)&As[buf][kk][ty * 8 + 4];
            ulonglong2 bb0 = *(const ulonglong2*)&Bs[buf][kk][tx * 8];
            ulonglong2 bb1 = *(const ulonglong2*)&Bs[buf][kk][tx * 8 + 4];
            unsigned long long bp[4] = {bb0.x, bb0.y, bb1.x, bb1.y};
            float av[8] = {a0.x, a0.y, a0.z, a0.w, a1.x, a1.y, a1.z, a1.w};
#pragma unroll
            for (int i = 0; i < 8; i++) {
                unsigned long long ad;
                asm("mov.b64 %0, {%1, %1};" : "=l"(ad) : "f"(av[i]));
#pragma unroll
                for (int j = 0; j < 4; j++)
                    asm("fma.rn.f32x2 %0, %1, %2, %3;"
                        : "=l"(acc[i][j]) : "l"(ad), "l"(bp[j]), "l"(acc[i][j]));
            }
        }

        if (kt < KTILES - 1) {
            storeTiles(buf ^ 1);     // hazard covered by previous iter's barrier
            __syncthreads();
            buf ^= 1;
        }
    }

    // epilogue: scale by d[b,o]; f32x2 pairs run along oc (lo=n, hi=n+1)
#pragma unroll
    for (int j2 = 0; j2 < 4; j2++) {
        int nlo = n0 + tx * 8 + j2 * 2;
        float d0 = g_d[b * 256 + nlo];
        float d1 = g_d[b * 256 + nlo + 1];
        float lo[8], hi[8];
#pragma unroll
        for (int i = 0; i < 8; i++) {
            lo[i] = __uint_as_float((unsigned)(acc[i][j2] & 0xffffffffull));
            hi[i] = __uint_as_float((unsigned)(acc[i][j2] >> 32));
        }
        float* op0 = out + ((size_t)(b * 256 + nlo)) * 4096 + m0 + ty * 8;
        float* op1 = op0 + 4096;
        ((float4*)op0)[0] = make_float4(lo[0] * d0, lo[1] * d0, lo[2] * d0, lo[3] * d0);
        ((float4*)op0)[1] = make_float4(lo[4] * d0, lo[5] * d0, lo[6] * d0, lo[7] * d0);
        ((float4*)op1)[0] = make_float4(hi[0] * d1, hi[1] * d1, hi[2] * d1, hi[3] * d1);
        ((float4*)op1)[1] = make_float4(hi[4] * d1, hi[5] * d1, hi[6] * d1, hi[7] * d1);
    }
}

extern "C" void kernel_launch(void* const* d_in, const int* in_sizes, int n_in,
                              void* d_out, int out_size) {
    const float* x      = (const float*)d_in[0];   // (8,256,64,64)
    const float* style  = (const float*)d_in[1];   // (8,512)
    const float* weight = (const float*)d_in[2];   // (1,256,256,3,3)
    const float* mod_w  = (const float*)d_in[3];   // (256,512)
    const float* mod_b  = (const float*)d_in[4];   // (256,)
    float* out = (float*)d_out;                    // (8,256,64,64)

    style_kernel<<<256, 256>>>(style, mod_w, mod_b);
    scale_x_kernel<<<8192, 256>>>(x);
    wtrans_kernel<<<KDIM, 256>>>(weight);
    demod_kernel<<<256, 256>>>(weight);

    dim3 grid(NPIX / 128, OC_ / 128, B_);
    conv_kernel<<<grid, 256>>>(out);
}

// round 17
// speedup vs baseline: 2.1417x; 2.1417x over previous
#include <cuda_runtime.h>
#include <cuda_bf16.h>
#include <cstdint>
#include <cstddef>

// ModulatedConv2d via mma.sync (HMMA) bf16 split-precision implicit GEMM.
// (tcgen05 is unavailable: harness PTX targets compute_103, no 'a' features.)
// out[b,o] = d[b,o] * conv( s'[b,i]*x[b,i], W[o,i] )
// GEMM: M=4096 px/batch, N=256 oc, K' = 3 segments * 2304.
// Segments: (x_hi,w_hi), (x_hi,w_lo), (x_lo,w_hi); lo*lo dropped (~1.5e-5 rel).

#define B_      8
#define NPIX    4096
#define KSEG    2304          // 9*256
#define BK      32
#define CPSEG   72            // 2304/32
#define NCHUNK  216           // 3*72

#define LIN_SCALE  0.044194173824159216f   // 1/sqrt(512)
#define CONV_SCALE 0.020833333333333332f   // 1/48

static __device__ float g_s[2048];
static __device__ float g_d[2048];
static __device__ __align__(16) __nv_bfloat16 g_xh[(size_t)B_*NPIX*256]; // [b][px][ic]
static __device__ __align__(16) __nv_bfloat16 g_xl[(size_t)B_*NPIX*256];
static __device__ __align__(16) __nv_bfloat16 g_wh[256*KSEG];            // [oc][tap*256+ic]
static __device__ __align__(16) __nv_bfloat16 g_wl[256*KSEG];

__device__ __forceinline__ uint32_t smem_u32(const void* p) {
    uint32_t a;
    asm("{ .reg .u64 t; cvta.to.shared.u64 t, %1; cvt.u32.u64 %0, t; }" : "=r"(a) : "l"(p));
    return a;
}
#define CP_ASYNC(sa, ga, nb) \
    asm volatile("cp.async.cg.shared.global [%0], [%1], 16, %2;" :: "r"(sa), "l"(ga), "r"(nb) : "memory")
#define CP_COMMIT() asm volatile("cp.async.commit_group;" ::: "memory")
#define CP_WAIT1()  asm volatile("cp.async.wait_group 1;" ::: "memory")
#define CP_WAIT0()  asm volatile("cp.async.wait_group 0;" ::: "memory")

#define LDSM_X4(d0,d1,d2,d3,addr) \
    asm volatile("ldmatrix.sync.aligned.m8n8.x4.shared.b16 {%0,%1,%2,%3}, [%4];" \
        : "=r"(d0),"=r"(d1),"=r"(d2),"=r"(d3) : "r"(addr))

#define MMA16816(c, a, b0, b1) \
    asm volatile("mma.sync.aligned.m16n8k16.row.col.f32.bf16.bf16.f32 " \
        "{%0,%1,%2,%3}, {%4,%5,%6,%7}, {%8,%9}, {%0,%1,%2,%3};" \
        : "+f"((c)[0]),"+f"((c)[1]),"+f"((c)[2]),"+f"((c)[3]) \
        : "r"((a)[0]),"r"((a)[1]),"r"((a)[2]),"r"((a)[3]), "r"(b0),"r"(b1))

// Conflict-free swizzle: 2 logical 64B rows per 128B line; slot = ((r&1)*4+g) ^ ((r>>1)&7).
// All 8-lane STS.128 / ldmatrix phases hit 8 distinct 16B slots (proven by coset argument).
__device__ __forceinline__ uint32_t swz(int r, int g) {
    return (uint32_t)(((r >> 1) << 7) + (((((r & 1) << 2) | g) ^ ((r >> 1) & 7)) << 4));
}

// ---------------- prep 1: styles ----------------
__global__ void style_kernel(const float* __restrict__ style,
                             const float* __restrict__ mod_w,
                             const float* __restrict__ mod_b) {
    int tid  = threadIdx.x, lane = tid & 31;
    int gw   = blockIdx.x * 8 + (tid >> 5);
    int b    = gw >> 8, c = gw & 255;
    const float* sp = style + b * 512;
    const float* mp = mod_w + c * 512;
    float acc = 0.f;
#pragma unroll
    for (int j = 0; j < 16; j++) acc += sp[lane + j * 32] * mp[lane + j * 32];
#pragma unroll
    for (int off = 16; off; off >>= 1) acc += __shfl_down_sync(0xffffffffu, acc, off);
    if (lane == 0) g_s[b * 256 + c] = (acc * LIN_SCALE + mod_b[c]) * CONV_SCALE;
}

// ---------------- prep 2: scale + split + transpose x ----------------
__global__ void xsplit_kernel(const float* __restrict__ x) {
    __shared__ float t[64][65];
    int b = blockIdx.z, ic0 = blockIdx.y * 64, px0 = blockIdx.x * 64;
    int tid = threadIdx.x;
#pragma unroll
    for (int it = 0; it < 16; it++) {
        int idx = tid + it * 256, i = idx >> 6, j = idx & 63;
        t[i][j] = x[((size_t)(b * 256 + ic0 + i) << 12) + px0 + j] * g_s[b * 256 + ic0 + i];
    }
    __syncthreads();
#pragma unroll
    for (int it = 0; it < 16; it++) {
        int idx = tid + it * 256, i = idx & 63, j = idx >> 6;
        float v = t[i][j];
        __nv_bfloat16 h = __float2bfloat16(v);
        __nv_bfloat16 l = __float2bfloat16(v - __bfloat162float(h));
        size_t a = ((size_t)b * 4096 + px0 + j) * 256 + ic0 + i;
        g_xh[a] = h; g_xl[a] = l;
    }
}

// ---------------- prep 3: split W ----------------
__global__ void wsplit_kernel(const float* __restrict__ W) {
    int oc = blockIdx.x, ic = threadIdx.x;
#pragma unroll
    for (int tap = 0; tap < 9; tap++) {
        float v = W[oc * 2304 + ic * 9 + tap];
        __nv_bfloat16 h = __float2bfloat16(v);
        __nv_bfloat16 l = __float2bfloat16(v - __bfloat162float(h));
        g_wh[oc * 2304 + tap * 256 + ic] = h;
        g_wl[oc * 2304 + tap * 256 + ic] = l;
    }
}

// ---------------- prep 4: demod (fp32, exact) ----------------
__global__ void demod_kernel(const float* __restrict__ W) {
    int o = blockIdx.x, i = threadIdx.x;
    const float* wp = W + o * 2304 + i * 9;
    float wsq = 0.f;
#pragma unroll
    for (int t = 0; t < 9; t++) wsq += wp[t] * wp[t];
    __shared__ float red[256];
#pragma unroll 1
    for (int b = 0; b < B_; b++) {
        float sv = g_s[b * 256 + i];
        red[i] = sv * sv * wsq;
        __syncthreads();
#pragma unroll
        for (int s = 128; s > 0; s >>= 1) {
            if (i < s) red[i] += red[i + s];
            __syncthreads();
        }
        if (i == 0) g_d[b * 256 + o] = rsqrtf(red[0] + 1e-8f);
        __syncthreads();
    }
}

// ---------------- main HMMA conv ----------------
// grid (32, 2, 8): 128 px x 128 oc tiles, 8 warps = 4(M)x2(N), warp 32x64.
__global__ __launch_bounds__(256, 1)
void conv_kernel(float* __restrict__ out) {
    __shared__ __align__(16) char As[2][8192];
    __shared__ __align__(16) char Bs[2][8192];

    const int tid = threadIdx.x, wid = tid >> 5, lane = tid & 31;
    const int wm = wid & 3, wn = wid >> 2;
    const int m0 = blockIdx.x * 128, n0 = blockIdx.y * 128, b = blockIdx.z;

    const uint32_t Ab[2] = { smem_u32(As[0]), smem_u32(As[1]) };
    const uint32_t Bb[2] = { smem_u32(Bs[0]), smem_u32(Bs[1]) };

    float acc[2][8][4];
#pragma unroll
    for (int t = 0; t < 2; t++)
#pragma unroll
        for (int n = 0; n < 8; n++)
#pragma unroll
            for (int j = 0; j < 4; j++) acc[t][n][j] = 0.f;

    // per-thread load coords: slot = tid + it*256 -> row = slot>>2, g = slot&3
    const int lr = tid >> 2, lg = tid & 3;           // it=0: rows 0-63
    // it=1: rows 64-127 (lr+64)

    auto load = [&](int stage, int c) {
        int seg = c / CPSEG, r2 = c % CPSEG;
        int tap = r2 >> 3, ic0 = (r2 & 7) * 32;
        int dh = tap / 3 - 1, dw = tap % 3 - 1;
        const __nv_bfloat16* xa = (seg < 2 ? g_xh : g_xl) + (size_t)b * NPIX * 256;
        const __nv_bfloat16* wb = (seg == 1 ? g_wl : g_wh);
#pragma unroll
        for (int it = 0; it < 2; it++) {
            int r = lr + it * 64;
            // A: pixel rows
            int px = m0 + r;
            int hh = (px >> 6) + dh, ww = (px & 63) + dw;
            bool ok = ((unsigned)hh < 64u) & ((unsigned)ww < 64u);
            const __nv_bfloat16* ga = xa + ((size_t)(ok ? hh * 64 + ww : 0)) * 256 + ic0 + lg * 8;
            CP_ASYNC(Ab[stage] + swz(r, lg), ga, ok ? 16 : 0);
            // B: oc rows
            const __nv_bfloat16* gb = wb + (size_t)(n0 + r) * KSEG + tap * 256 + ic0 + lg * 8;
            CP_ASYNC(Bb[stage] + swz(r, lg), gb, 16);
        }
    };

    load(0, 0);
    CP_COMMIT();

#pragma unroll 1
    for (int c = 0; c < NCHUNK; c++) {
        const int st = c & 1;
        if (c + 1 < NCHUNK) { load(st ^ 1, c + 1); CP_COMMIT(); CP_WAIT1(); }
        else                { CP_WAIT0(); }
        __syncthreads();

#pragma unroll
        for (int ks = 0; ks < 2; ks++) {
            const int gg = ks * 2 + (lane >> 4);
            uint32_t a_r[2][4], b_r[4][4];
#pragma unroll
            for (int t = 0; t < 2; t++) {
                int rl = wm * 32 + t * 16 + (lane & 15);
                LDSM_X4(a_r[t][0], a_r[t][1], a_r[t][2], a_r[t][3], Ab[st] + swz(rl, gg));
            }
#pragma unroll
            for (int p = 0; p < 4; p++) {
                int rl = wn * 64 + p * 16 + (lane & 15);
                LDSM_X4(b_r[p][0], b_r[p][1], b_r[p][2], b_r[p][3], Bb[st] + swz(rl, gg));
            }
#pragma unroll
            for (int t = 0; t < 2; t++)
#pragma unroll
                for (int nt = 0; nt < 8; nt++) {
                    int p = nt >> 1, o = nt & 1;
                    MMA16816(acc[t][nt], a_r[t], b_r[p][o], b_r[p][o + 2]);
                }
        }
        __syncthreads();
    }

    // epilogue: c0/c1 -> (row, col/col+1), c2/c3 -> (row+8, col/col+1)
    const int row = lane >> 2, col2 = (lane & 3) * 2;
    float* ob = out + ((size_t)b * 256) * 4096;
#pragma unroll
    for (int t = 0; t < 2; t++) {
        int pxb = m0 + wm * 32 + t * 16 + row;
#pragma unroll
        for (int nt = 0; nt < 8; nt++) {
            int oc0 = n0 + wn * 64 + nt * 8 + col2;
            float d0 = __ldg(&g_d[b * 256 + oc0]);
            float d1 = __ldg(&g_d[b * 256 + oc0 + 1]);
            ob[(size_t)oc0 * 4096 + pxb]           = acc[t][nt][0] * d0;
            ob[(size_t)(oc0 + 1) * 4096 + pxb]     = acc[t][nt][1] * d1;
            ob[(size_t)oc0 * 4096 + pxb + 8]       = acc[t][nt][2] * d0;
            ob[(size_t)(oc0 + 1) * 4096 + pxb + 8] = acc[t][nt][3] * d1;
        }
    }
}

extern "C" void kernel_launch(void* const* d_in, const int* in_sizes, int n_in,
                              void* d_out, int out_size) {
    const float* x      = (const float*)d_in[0];   // (8,256,64,64)
    const float* style  = (const float*)d_in[1];   // (8,512)
    const float* weight = (const float*)d_in[2];   // (1,256,256,3,3)
    const float* mod_w  = (const float*)d_in[3];   // (256,512)
    const float* mod_b  = (const float*)d_in[4];   // (256,)
    float* out = (float*)d_out;                    // (8,256,64,64)

    style_kernel<<<256, 256>>>(style, mod_w, mod_b);
    xsplit_kernel<<<dim3(64, 4, 8), 256>>>(x);
    wsplit_kernel<<<256, 256>>>(weight);
    demod_kernel<<<256, 256>>>(weight);
    conv_kernel<<<dim3(32, 2, 8), 256>>>(out);
}